// round 6
// baseline (speedup 1.0000x reference)
#include <cuda_runtime.h>
#include <cstdint>

// Problem constants
#define NUM_PROPERTIES 10000
#define HDIM 512
#define ODIM 2
#define BATCH 512
#define NUM_PROPS 128
#define NROWS (BATCH * NUM_PROPS)   // 65536 (b,p) rows

#define NSM 148
#define CTAS_PER_SM 8
#define GRID_CTAS (NSM * CTAS_PER_SM)            // 1184
#define TOTAL_WARPS (GRID_CTAS * 8)              // 9472

#define BIN_CAP 32   // Poisson(6.55): P(count>32) ~ 1e-15; spill path covers the rest

// Scratch (static device globals; no allocation)
__device__ int g_counts[NUM_PROPERTIES];
__device__ int g_bins[NUM_PROPERTIES * BIN_CAP];   // 1.28 MB
__device__ int g_spill[NROWS];                     // worst case: all rows spill
__device__ int g_nspill;

// ---------------------------------------------------------------------------
__global__ void zero_kernel() {
    int i = blockIdx.x * blockDim.x + threadIdx.x;
    if (i < NUM_PROPERTIES) g_counts[i] = 0;
    if (i == 0) g_nspill = 0;
}

// Dtype self-detection helper (properties may be int32 or int64): warp reads
// the first 256 bytes as int64 and ballots range-validity. int32 data passing
// requires 32 consecutive odd-index props == 0 (~1e-128). Deterministic.
__device__ __forceinline__ bool detect_is64(const int* props, int lane) {
    const long long* p64 = (const long long*)props;
    long long probe = p64[lane];
    bool ok = (probe >= 0) && (probe < NUM_PROPERTIES);
    return __ballot_sync(0xffffffffu, ok) == 0xffffffffu;
}

__global__ void scatter_kernel(const int* __restrict__ props) {
    const int lane = threadIdx.x & 31;
    const bool is64 = detect_is64(props, lane);
    const long long* p64 = (const long long*)props;

    for (int row = blockIdx.x * blockDim.x + threadIdx.x; row < NROWS;
         row += gridDim.x * blockDim.x) {
        int prop = is64 ? (int)p64[row] : props[row];
        int pos = atomicAdd(&g_counts[prop], 1);
        if (pos < BIN_CAP) {
            g_bins[prop * BIN_CAP + pos] = row;
        } else {
            int s = atomicAdd(&g_nspill, 1);
            g_spill[s] = row;
        }
    }
}

// ---------------------------------------------------------------------------
__device__ __forceinline__ float2 ldcs_f2(const float2* p) {
    float2 v;
    asm volatile("ld.global.cs.v2.f32 {%0,%1}, [%2];"
                 : "=f"(v.x), "=f"(v.y) : "l"(p));
    return v;
}

// One row: warp-cooperative dot product (wavefront-minimal layout from R3):
//   W row = 256 float4; lane handles j = lane + 32k, k = 0..7 (contiguous
//   warp-wide); h row = 256 float2 paired 1:1 with W float4s.
// h streamed evict-first; W default-cached (L1 hit for rows 2..n of a bin).
__device__ __forceinline__ void process_row(
    int row, int prop, int lane,
    const float* __restrict__ hs, const float* __restrict__ mask,
    const float4* __restrict__ w4, const float* __restrict__ bias,
    float* __restrict__ out)
{
    const float2* __restrict__ h2 = (const float2*)(hs + (size_t)row * HDIM);

    float acc0 = 0.0f, acc1 = 0.0f;
    #pragma unroll 4
    for (int k = 0; k < 8; k++) {
        const int j = lane + 32 * k;
        const float2 h = ldcs_f2(&h2[j]);   // streaming: evict-first
        const float4 w = w4[j];             // cached: L1-hot within a bin
        acc0 = fmaf(h.x, w.x, acc0);
        acc1 = fmaf(h.x, w.y, acc1);
        acc0 = fmaf(h.y, w.z, acc0);
        acc1 = fmaf(h.y, w.w, acc1);
    }

    #pragma unroll
    for (int off = 16; off > 0; off >>= 1) {
        acc0 += __shfl_xor_sync(0xffffffff, acc0, off);
        acc1 += __shfl_xor_sync(0xffffffff, acc1, off);
    }

    if (lane == 0) {
        const float m  = mask[row];
        const float b0 = bias[prop * 2 + 0];
        const float b1 = bias[prop * 2 + 1];
        float2 r;
        r.x = (acc0 + b0) * m;
        r.y = (acc1 + b1) * m;
        asm volatile("st.global.cs.v2.f32 [%0], {%1,%2};"
                     :: "l"(((float2*)out) + row), "f"(r.x), "f"(r.y));
    }
}

// Binned GEMV: one warp per property -> W row read from L2 once per bin
// (L1 hits for the bin's remaining rows), cutting L2/LTS traffic ~2x.
// Spill rows (bin overflow, ~never for random props) processed row-wise after.
// Every row lands in exactly one of {bin, spill}, and per-row math is
// order-independent -> output is bitwise identical across runs.
__global__ __launch_bounds__(256, CTAS_PER_SM)
void binned_gemv_kernel(
    const float*  __restrict__ hs,     // (B, P, H)
    const int*    __restrict__ props,  // (B, P) int32/int64
    const float*  __restrict__ mask,   // (B, P)
    const float*  __restrict__ W,      // (NUM_PROPERTIES, H, 2)
    const float*  __restrict__ bias,   // (NUM_PROPERTIES, 2)
    float*        __restrict__ out)    // (B, P, 2)
{
    const int lane  = threadIdx.x & 31;
    const int gwarp = (blockIdx.x * blockDim.x + threadIdx.x) >> 5;
    const bool is64 = detect_is64(props, lane);
    const long long* p64 = (const long long*)props;

    // Phase 1: bins (one warp owns each property)
    for (int p = gwarp; p < NUM_PROPERTIES; p += TOTAL_WARPS) {
        int n = g_counts[p];
        if (n <= 0) continue;
        if (n > BIN_CAP) n = BIN_CAP;
        const float4* __restrict__ w4 =
            (const float4*)(W + (size_t)p * (HDIM * ODIM));
        for (int i = 0; i < n; i++) {
            const int row = g_bins[p * BIN_CAP + i];
            process_row(row, p, lane, hs, mask, w4, bias, out);
        }
    }

    // Phase 2: spill rows (overflowed bins), one warp per row
    const int ns = g_nspill;
    for (int s = gwarp; s < ns; s += TOTAL_WARPS) {
        const int row = g_spill[s];
        const int prop = is64 ? (int)p64[row] : props[row];
        const float4* __restrict__ w4 =
            (const float4*)(W + (size_t)prop * (HDIM * ODIM));
        process_row(row, prop, lane, hs, mask, w4, bias, out);
    }
}

// ---------------------------------------------------------------------------
extern "C" void kernel_launch(void* const* d_in, const int* in_sizes, int n_in,
                              void* d_out, int out_size) {
    const float* hs    = (const float*)d_in[0];   // hidden_states (512,128,512) f32
    const int*   props = (const int*)d_in[1];     // properties (512,128)
    const float* mask  = (const float*)d_in[2];   // mask (512,128) f32
    const float* W     = (const float*)d_in[3];   // classifier_weights (10000,512,2) f32
    const float* bias  = (const float*)d_in[4];   // classifier_bias (10000,2) f32
    float*       out   = (float*)d_out;           // (512,128,2) f32

    zero_kernel<<<(NUM_PROPERTIES + 255) / 256, 256>>>();
    scatter_kernel<<<256, 256>>>(props);
    binned_gemv_kernel<<<GRID_CTAS, 256>>>(hs, props, mask, W, bias, out);
}

// round 7
// speedup vs baseline: 2.3216x; 2.3216x over previous
#include <cuda_runtime.h>
#include <cstdint>

// Problem constants
#define NUM_PROPERTIES 10000
#define HDIM 512
#define ODIM 2
#define BATCH 512
#define NUM_PROPS 128
#define NROWS (BATCH * NUM_PROPS)   // 65536 (b,p) rows

#define NSM 148
#define CTAS_PER_SM 6
#define GRID_CTAS (NSM * CTAS_PER_SM)            // 888 -> exactly one wave
#define WARPS_PER_CTA 8
#define TOTAL_WARPS (GRID_CTAS * WARPS_PER_CTA)  // 7104

__device__ __forceinline__ float2 ldcs_f2(const float2* p) {
    float2 v;
    asm volatile("ld.global.cs.v2.f32 {%0,%1}, [%2];"
                 : "=f"(v.x), "=f"(v.y) : "l"(p));
    return v;
}

// Persistent grid-stride kernel; one warp per (b,p) row per iteration.
// (R6 post-mortem: property-binned reordering regressed 2.7x and is EV-negative
//  even in the best case -- DRAM bytes are already at the compulsory floor.
//  This is the R4 structure with deeper load batching.)
//
// Dtype self-detection (properties may be int32 or int64 depending on JAX
// x64 config): every warp reads p64[lane] (first 256 bytes, in-bounds under
// both interpretations) and ballots whether all 32 values lie in
// [0, NUM_PROPERTIES). int32 data passing this requires 32 consecutive
// odd-index props to be zero (~1e-128). Deterministic, identical across warps.
//
// Memory layout per row (wavefront-minimal, see R3):
//   W row = 256 float4; lane handles j = lane + 32k, k = 0..7 (contiguous
//   warp-wide, 4 wavefronts/instr); h row = 256 float2 paired 1:1 with W
//   float4s (2 wavefronts/instr).
// hidden_states + out use evict-first (.cs) so the 40 MiB W table stays in L2.
//
// R7 change: full unroll (16 loads batched per row) + __launch_bounds__(256,6)
// (~42-reg budget) -> per-warp MLP ~2x at 48 warps/SM; net in-flight bytes
// +50% to raise DRAM duty cycle under the LTS-congested regime.
__global__ __launch_bounds__(256, CTAS_PER_SM)
void adapter_gemv_kernel(
    const float*  __restrict__ hs,     // (B, P, H)
    const int*    __restrict__ props,  // (B, P) int32 or int64 (detected)
    const float*  __restrict__ mask,   // (B, P)
    const float*  __restrict__ W,      // (NUM_PROPERTIES, H, 2)
    const float2* __restrict__ bias,   // (NUM_PROPERTIES, 2) viewed as float2
    float*        __restrict__ out)    // (B, P, 2)
{
    const int lane   = threadIdx.x & 31;
    const int gwarp0 = (blockIdx.x * blockDim.x + threadIdx.x) >> 5;

    // --- per-warp dtype detection (one broadcast 256B window) ---
    const long long* p64 = (const long long*)props;
    long long probe = p64[lane];
    bool in_range = (probe >= 0) && (probe < NUM_PROPERTIES);
    const bool is64 = (__ballot_sync(0xffffffffu, in_range) == 0xffffffffu);

    for (int row = gwarp0; row < NROWS; row += TOTAL_WARPS) {
        long long prop;
        if (is64) prop = p64[row];
        else      prop = (long long)props[row];

        const float2* __restrict__ h2 = (const float2*)(hs + (size_t)row * HDIM);
        const float4* __restrict__ w4 = (const float4*)(W + (size_t)prop * (HDIM * ODIM));

        float acc0 = 0.0f, acc1 = 0.0f;
        #pragma unroll
        for (int k = 0; k < 8; k++) {
            const int j = lane + 32 * k;
            const float2 h = ldcs_f2(&h2[j]);   // streaming: evict-first
            const float4 w = w4[j];             // default: keep in L2
            acc0 = fmaf(h.x, w.x, acc0);
            acc1 = fmaf(h.x, w.y, acc1);
            acc0 = fmaf(h.y, w.z, acc0);
            acc1 = fmaf(h.y, w.w, acc1);
        }

        #pragma unroll
        for (int off = 16; off > 0; off >>= 1) {
            acc0 += __shfl_xor_sync(0xffffffff, acc0, off);
            acc1 += __shfl_xor_sync(0xffffffff, acc1, off);
        }

        if (lane == 0) {
            const float  m = mask[row];
            const float2 b = bias[prop];   // one aligned 8B load
            float2 r;
            r.x = (acc0 + b.x) * m;
            r.y = (acc1 + b.y) * m;
            asm volatile("st.global.cs.v2.f32 [%0], {%1,%2};"
                         :: "l"(((float2*)out) + row), "f"(r.x), "f"(r.y));
        }
    }
}

extern "C" void kernel_launch(void* const* d_in, const int* in_sizes, int n_in,
                              void* d_out, int out_size) {
    const float*  hs    = (const float*)d_in[0];   // hidden_states (512,128,512) f32
    const int*    props = (const int*)d_in[1];     // properties (512,128)
    const float*  mask  = (const float*)d_in[2];   // mask (512,128) f32
    const float*  W     = (const float*)d_in[3];   // classifier_weights (10000,512,2) f32
    const float2* bias  = (const float2*)d_in[4];  // classifier_bias (10000,2) f32
    float*        out   = (float*)d_out;           // (512,128,2) f32

    adapter_gemv_kernel<<<GRID_CTAS, 256>>>(hs, props, mask, W, bias, out);
}

// round 8
// speedup vs baseline: 2.6678x; 1.1491x over previous
#include <cuda_runtime.h>
#include <cstdint>

// Problem constants
#define NUM_PROPERTIES 10000
#define HDIM 512
#define ODIM 2
#define BATCH 512
#define NUM_PROPS 128
#define NROWS (BATCH * NUM_PROPS)   // 65536 (b,p) rows

#define NSM 148
#define CTAS_PER_SM 8
#define GRID_CTAS (NSM * CTAS_PER_SM)            // 1184
#define WARPS_PER_CTA 8
#define TOTAL_WARPS (GRID_CTAS * WARPS_PER_CTA)  // 9472

__device__ __forceinline__ float2 ldcs_f2(const float2* p) {
    float2 v;
    asm volatile("ld.global.cs.v2.f32 {%0,%1}, [%2];"
                 : "=f"(v.x), "=f"(v.y) : "l"(p));
    return v;
}

// Persistent grid-stride kernel; one warp per (b,p) row per iteration.
// This is the R4 configuration (best measured: 29.15us), which sits at the
// chip-wide LTS throughput cap (~400 MB of L2 traffic at ~6300 B/cyc) with
// DRAM bytes at the compulsory floor (~179 MB). Experiments bracketing it:
//   R5 prefetch-pipeline: neutral/worse (warp pool already hides latency)
//   R6 property-binned reorder: 2.7x regression (and EV-negative even ideal)
//   R7 full-unroll @ 6 CTAs/SM: 15% regression (occupancy > per-warp MLP)
// => 64 warps/SM + unroll 4 is the operating point; only micro-fixes below.
//
// Dtype self-detection (properties may be int32 or int64 depending on JAX
// x64 config): every warp reads p64[lane] (first 256 bytes, in-bounds under
// both interpretations) and ballots whether all 32 values lie in
// [0, NUM_PROPERTIES). int32 data passing this requires 32 consecutive
// odd-index props to be zero (~1e-128). Deterministic, identical across warps.
//
// Memory layout per row (wavefront-minimal):
//   W row = 256 float4; lane handles j = lane + 32k, k = 0..7 (contiguous
//   warp-wide, 4 wavefronts/instr); h row = 256 float2 paired 1:1 with W
//   float4s (2 wavefronts/instr).
// hidden_states + out use evict-first (.cs) so the 40 MiB W table stays in L2.
__global__ __launch_bounds__(256, CTAS_PER_SM)
void adapter_gemv_kernel(
    const float*  __restrict__ hs,     // (B, P, H)
    const int*    __restrict__ props,  // (B, P) int32 or int64 (detected)
    const float*  __restrict__ mask,   // (B, P)
    const float*  __restrict__ W,      // (NUM_PROPERTIES, H, 2)
    const float2* __restrict__ bias,   // (NUM_PROPERTIES, 2) viewed as float2
    float*        __restrict__ out)    // (B, P, 2)
{
    const int lane   = threadIdx.x & 31;
    const int gwarp0 = (blockIdx.x * blockDim.x + threadIdx.x) >> 5;

    // --- per-warp dtype detection (one broadcast 256B window) ---
    const long long* p64 = (const long long*)props;
    long long probe = p64[lane];
    bool in_range = (probe >= 0) && (probe < NUM_PROPERTIES);
    const bool is64 = (__ballot_sync(0xffffffffu, in_range) == 0xffffffffu);

    for (int row = gwarp0; row < NROWS; row += TOTAL_WARPS) {
        long long prop;
        if (is64) prop = p64[row];
        else      prop = (long long)props[row];

        const float2* __restrict__ h2 = (const float2*)(hs + (size_t)row * HDIM);
        const float4* __restrict__ w4 = (const float4*)(W + (size_t)prop * (HDIM * ODIM));

        float acc0 = 0.0f, acc1 = 0.0f;
        #pragma unroll 4
        for (int k = 0; k < 8; k++) {
            const int j = lane + 32 * k;
            const float2 h = ldcs_f2(&h2[j]);   // streaming: evict-first
            const float4 w = w4[j];             // default: keep in L2
            acc0 = fmaf(h.x, w.x, acc0);
            acc1 = fmaf(h.x, w.y, acc1);
            acc0 = fmaf(h.y, w.z, acc0);
            acc1 = fmaf(h.y, w.w, acc1);
        }

        #pragma unroll
        for (int off = 16; off > 0; off >>= 1) {
            acc0 += __shfl_xor_sync(0xffffffff, acc0, off);
            acc1 += __shfl_xor_sync(0xffffffff, acc1, off);
        }

        if (lane == 0) {
            const float  m = mask[row];
            const float2 b = bias[prop];   // one aligned 8B load
            float2 r;
            r.x = (acc0 + b.x) * m;
            r.y = (acc1 + b.y) * m;
            asm volatile("st.global.cs.v2.f32 [%0], {%1,%2};"
                         :: "l"(((float2*)out) + row), "f"(r.x), "f"(r.y));
        }
    }
}

extern "C" void kernel_launch(void* const* d_in, const int* in_sizes, int n_in,
                              void* d_out, int out_size) {
    const float*  hs    = (const float*)d_in[0];   // hidden_states (512,128,512) f32
    const int*    props = (const int*)d_in[1];     // properties (512,128)
    const float*  mask  = (const float*)d_in[2];   // mask (512,128) f32
    const float*  W     = (const float*)d_in[3];   // classifier_weights (10000,512,2) f32
    const float2* bias  = (const float2*)d_in[4];  // classifier_bias (10000,2) f32
    float*        out   = (float*)d_out;           // (512,128,2) f32

    adapter_gemv_kernel<<<GRID_CTAS, 256>>>(hs, props, mask, W, bias, out);
}